// round 7
// baseline (speedup 1.0000x reference)
#include <cuda_runtime.h>
#include <math.h>

#define B_ 16384
#define S_ 32
#define D_ 64
#define KTOP 3

constexpr int SD = S_ * D_;
constexpr long long OFF_READ_R = 0;
constexpr long long OFF_READ_I = (long long)B_ * D_;
constexpr long long OFF_NEXT_R = 2LL * B_ * D_;
constexpr long long OFF_NEXT_I = OFF_NEXT_R + (long long)B_ * SD;
constexpr long long OFF_ENT    = OFF_NEXT_I + (long long)B_ * SD;

__global__ void am_init_kernel(float* __restrict__ out) {
    out[OFF_ENT] = 0.0f;
}

__device__ __forceinline__ float dot4(float4 a, float4 b) {
    float s = a.x * b.x;
    s = fmaf(a.y, b.y, s);
    s = fmaf(a.z, b.z, s);
    s = fmaf(a.w, b.w, s);
    return s;
}

__global__ __launch_bounds__(256, 5) void am_fused_kernel(
    const float* __restrict__ gw_r,  const float* __restrict__ gw_i,
    const float* __restrict__ mem_r, const float* __restrict__ mem_i,
    const float* __restrict__ Wg,    const float* __restrict__ bg,
    const float* __restrict__ Wa,    const float* __restrict__ ba,
    const float* __restrict__ gamma_r, const float* __restrict__ beta_r,
    const float* __restrict__ gamma_i, const float* __restrict__ beta_i,
    float* __restrict__ out)
{
    __shared__ float sim[S_];
    __shared__ float wlog[8][S_];   // per-warp logit partials
    __shared__ float pr[8][D_];     // per-warp read_r partials
    __shared__ float pi_[8][D_];    // per-warp read_i partials

    const int t    = threadIdx.x;
    const int b    = blockIdx.x;
    const int warp = t >> 5;
    const int lane = t & 31;
    const int sub  = t & 15;        // cols 4*sub..4*sub+3
    const int rA   = t >> 4;        // row 0..15 ; rB = rA+16
    const long long baseSD = (long long)b * SD;

    // ---- mem rows -> registers (contiguous vec4, max MLP) ----
    const float4* m4r = (const float4*)(mem_r + baseSD);
    const float4* m4i = (const float4*)(mem_i + baseSD);
    const float4 mrA = m4r[t];
    const float4 mrB = m4r[t + 256];
    const float4 miA = m4i[t];
    const float4 miB = m4i[t + 256];

    // ---- gw slices straight into registers (each warp holds all 128) ----
    const float4 gwr4 = ((const float4*)(gw_r + (long long)b * D_))[sub];
    const float4 gwi4 = ((const float4*)(gw_i + (long long)b * D_))[sub];

    // ---- sim partials for rows rA, rA+16 ----
    {
        float accA = dot4(mrA, gwr4) + dot4(miA, gwi4);
        float accB = dot4(mrB, gwr4) + dot4(miB, gwi4);
        #pragma unroll
        for (int o = 8; o; o >>= 1) {
            accA += __shfl_xor_sync(0xffffffffu, accA, o);
            accB += __shfl_xor_sync(0xffffffffu, accB, o);
        }
        if (sub == 0) {
            sim[rA]      = accA;
            sim[rA + 16] = accB;
        }
    }

    // ---- logit partials: warp w owns j in [16w,16w+16), lane l owns slot l ----
    {
        float lacc = 0.0f;
        const int jbase = warp * 16;
        #pragma unroll
        for (int i = 0; i < 16; i++) {
            // flat[jbase+i]: fetch from register-resident gw via shfl.
            // component (i&3) is compile-time; source lane is warp-uniform.
            float f;
            if (warp < 4) {
                const int src = 4 * warp + (i >> 2);
                const float c = (i & 3) == 0 ? gwr4.x : (i & 3) == 1 ? gwr4.y
                              : (i & 3) == 2 ? gwr4.z : gwr4.w;
                f = __shfl_sync(0xffffffffu, c, src);
            } else {
                const int src = 4 * (warp - 4) + (i >> 2);
                const float c = (i & 3) == 0 ? gwi4.x : (i & 3) == 1 ? gwi4.y
                              : (i & 3) == 2 ? gwi4.z : gwi4.w;
                f = __shfl_sync(0xffffffffu, c, src);
            }
            lacc = fmaf(f, Wa[(jbase + i) * S_ + lane], lacc);
        }
        wlog[warp][lane] = lacc;
    }
    __syncthreads();   // sim + wlog visible

    // ---- EVERY warp redundantly computes attn, sparse, gate (no 2nd barrier) ----
    float attn_l;   // lane l holds attn[l]
    {
        const float v = sim[lane];
        float m = v;
        #pragma unroll
        for (int o = 16; o; o >>= 1) m = fmaxf(m, __shfl_xor_sync(0xffffffffu, m, o));
        const float e = __expf(v - m);
        float ssum = e;
        #pragma unroll
        for (int o = 16; o; o >>= 1) ssum += __shfl_xor_sync(0xffffffffu, ssum, o);
        attn_l = e / ssum;
    }

    float sparse_l; // lane l holds sparse[l]
    {
        float v = ba[lane];
        #pragma unroll
        for (int w = 0; w < 8; w++) v += wlog[w][lane];
        float m = v;
        #pragma unroll
        for (int o = 16; o; o >>= 1) m = fmaxf(m, __shfl_xor_sync(0xffffffffu, m, o));
        const float e = __expf(v - m);
        float ssum = e;
        #pragma unroll
        for (int o = 16; o; o >>= 1) ssum += __shfl_xor_sync(0xffffffffu, ssum, o);
        const float w_ = e / ssum;

        if (warp == 0) {  // entropy: only one warp contributes
            float ent = -w_ * __logf(w_ + 1e-10f);
            #pragma unroll
            for (int o = 16; o; o >>= 1) ent += __shfl_xor_sync(0xffffffffu, ent, o);
            if (lane == 0) atomicAdd(out + OFF_ENT, ent * (1.0f / (float)B_));
        }

        float vv = w_;
        float sp = 0.0f;
        float sumTop = 0.0f;
        #pragma unroll
        for (int k = 0; k < KTOP; k++) {
            float mv = vv;
            int   mi = lane;
            #pragma unroll
            for (int o = 16; o; o >>= 1) {
                const float ov = __shfl_xor_sync(0xffffffffu, mv, o);
                const int   oi = __shfl_xor_sync(0xffffffffu, mi, o);
                if (ov > mv || (ov == mv && oi < mi)) { mv = ov; mi = oi; }
            }
            sumTop += mv;
            if (lane == mi) { sp = mv; vv = -INFINITY; }
        }
        sparse_l = sp / (sumTop + 1e-6f);
    }

    float s_wg;     // every lane gets the gate
    {
        const float4 wg0 = ((const float4*)Wg)[sub];
        const float4 wg1 = ((const float4*)(Wg + D_))[sub];
        float acc = dot4(gwr4, wg0) + dot4(gwi4, wg1);
        #pragma unroll
        for (int o = 8; o; o >>= 1) acc += __shfl_xor_sync(0xffffffffu, acc, o);
        s_wg = 1.0f / (1.0f + __expf(-(acc + bg[0])));
    }

    // gather per-row attn / sparse via shfl (rA, rB are lane-dependent but valid srcs)
    const float aA = __shfl_sync(0xffffffffu, attn_l, rA & 31);
    const float aB = __shfl_sync(0xffffffffu, attn_l, (rA + 16) & 31);
    const float spA = __shfl_sync(0xffffffffu, sparse_l, rA & 31);
    const float spB = __shfl_sync(0xffffffffu, sparse_l, (rA + 16) & 31);

    // ---- read-vector partials ----
    {
        float vr[4] = { aA*mrA.x + aB*mrB.x, aA*mrA.y + aB*mrB.y,
                        aA*mrA.z + aB*mrB.z, aA*mrA.w + aB*mrB.w };
        float vi[4] = { aA*miA.x + aB*miB.x, aA*miA.y + aB*miB.y,
                        aA*miA.z + aB*miB.z, aA*miA.w + aB*miB.w };
        #pragma unroll
        for (int i = 0; i < 4; i++) {
            vr[i] += __shfl_xor_sync(0xffffffffu, vr[i], 16);
            vi[i] += __shfl_xor_sync(0xffffffffu, vi[i], 16);
        }
        if (lane < 16) {
            ((float4*)&pr[warp][0])[lane]  = make_float4(vr[0], vr[1], vr[2], vr[3]);
            ((float4*)&pi_[warp][0])[lane] = make_float4(vi[0], vi[1], vi[2], vi[3]);
        }
    }

    // ---- memory update + LayerNorm ----
    {
        const float effA = s_wg * spA, omA = 1.0f - effA;
        const float effB = s_wg * spB, omB = 1.0f - effB;

        const float4 gr4 = ((const float4*)gamma_r)[sub];
        const float4 br4 = ((const float4*)beta_r)[sub];
        const float4 gi4 = ((const float4*)gamma_i)[sub];
        const float4 bi4 = ((const float4*)beta_i)[sub];

        float4* outR = (float4*)(out + OFF_NEXT_R + baseSD);
        float4* outI = (float4*)(out + OFF_NEXT_I + baseSD);

        #pragma unroll
        for (int part = 0; part < 4; part++) {
            const float4 src = (part == 0) ? mrA : (part == 1) ? mrB
                             : (part == 2) ? miA : miB;
            const float4 g   = (part < 2) ? gwr4 : gwi4;
            const float  eff = (part & 1) ? effB : effA;
            const float  om  = (part & 1) ? omB  : omA;

            const float v0 = om * src.x + eff * g.x;
            const float v1 = om * src.y + eff * g.y;
            const float v2 = om * src.z + eff * g.z;
            const float v3 = om * src.w + eff * g.w;

            float sum = v0 + v1 + v2 + v3;
            float sq  = fmaf(v0, v0, fmaf(v1, v1, fmaf(v2, v2, v3 * v3)));
            #pragma unroll
            for (int o = 8; o; o >>= 1) {
                sum += __shfl_xor_sync(0xffffffffu, sum, o);
                sq  += __shfl_xor_sync(0xffffffffu, sq, o);
            }
            const float mean = sum * (1.0f / 64.0f);
            const float var  = sq * (1.0f / 64.0f) - mean * mean;
            const float rstd = rsqrtf(var + 1e-5f);

            const float4 gam = (part < 2) ? gr4 : gi4;
            const float4 bet = (part < 2) ? br4 : bi4;
            float4 o4;
            o4.x = fmaf((v0 - mean) * rstd, gam.x, bet.x);
            o4.y = fmaf((v1 - mean) * rstd, gam.y, bet.y);
            o4.z = fmaf((v2 - mean) * rstd, gam.z, bet.z);
            o4.w = fmaf((v3 - mean) * rstd, gam.w, bet.w);

            float4* dst = (part < 2) ? outR : outI;
            dst[(part & 1) ? (t + 256) : t] = o4;
        }
    }

    // ---- final read-vector reduction ----
    __syncthreads();
    if (t < 128) {
        const int d = t & 63;
        const float* src = (t < 64) ? &pr[0][0] : &pi_[0][0];
        float s = 0.0f;
        #pragma unroll
        for (int w = 0; w < 8; w++) s += src[w * D_ + d];
        const long long off = ((t < 64) ? OFF_READ_R : OFF_READ_I) + (long long)b * D_ + d;
        out[off] = s;
    }
}

extern "C" void kernel_launch(void* const* d_in, const int* in_sizes, int n_in,
                              void* d_out, int out_size)
{
    const float* gw_r    = (const float*)d_in[0];
    const float* gw_i    = (const float*)d_in[1];
    const float* mem_r   = (const float*)d_in[2];
    const float* mem_i   = (const float*)d_in[3];
    const float* Wg      = (const float*)d_in[4];
    const float* bg      = (const float*)d_in[5];
    const float* Wa      = (const float*)d_in[6];
    const float* ba      = (const float*)d_in[7];
    const float* gamma_r = (const float*)d_in[8];
    const float* beta_r  = (const float*)d_in[9];
    const float* gamma_i = (const float*)d_in[10];
    const float* beta_i  = (const float*)d_in[11];
    float* out = (float*)d_out;

    am_init_kernel<<<1, 1>>>(out);
    am_fused_kernel<<<B_, 256>>>(gw_r, gw_i, mem_r, mem_i, Wg, bg, Wa, ba,
                                 gamma_r, beta_r, gamma_i, beta_i, out);
}

// round 8
// speedup vs baseline: 1.2089x; 1.2089x over previous
#include <cuda_runtime.h>
#include <math.h>

#define B_ 16384
#define S_ 32
#define D_ 64
#define KTOP 3

constexpr int SD = S_ * D_;
constexpr long long OFF_READ_R = 0;
constexpr long long OFF_READ_I = (long long)B_ * D_;
constexpr long long OFF_NEXT_R = 2LL * B_ * D_;
constexpr long long OFF_NEXT_I = OFF_NEXT_R + (long long)B_ * SD;
constexpr long long OFF_ENT    = OFF_NEXT_I + (long long)B_ * SD;

__global__ void am_init_kernel(float* __restrict__ out) {
    out[OFF_ENT] = 0.0f;
}

__device__ __forceinline__ float dot4(float4 a, float4 b) {
    float s = a.x * b.x;
    s = fmaf(a.y, b.y, s);
    s = fmaf(a.z, b.z, s);
    s = fmaf(a.w, b.w, s);
    return s;
}

__global__ __launch_bounds__(256, 5) void am_fused_kernel(
    const float* __restrict__ gw_r,  const float* __restrict__ gw_i,
    const float* __restrict__ mem_r, const float* __restrict__ mem_i,
    const float* __restrict__ Wg,    const float* __restrict__ bg,
    const float* __restrict__ Wa,    const float* __restrict__ ba,
    const float* __restrict__ gamma_r, const float* __restrict__ beta_r,
    const float* __restrict__ gamma_i, const float* __restrict__ beta_i,
    float* __restrict__ out)
{
    __shared__ float gwr[D_], gwi[D_];
    __shared__ float sim[S_], attn[S_], sparse[S_];
    __shared__ float wlog[8][S_];      // per-warp logit partials
    __shared__ float pr[8][D_];        // per-warp read_r partials
    __shared__ float pi_[8][D_];       // per-warp read_i partials
    __shared__ float s_wg;

    const int t    = threadIdx.x;
    const int b    = blockIdx.x;
    const int warp = t >> 5;
    const int lane = t & 31;
    const int sub  = t & 15;           // column group: cols 4*sub..4*sub+3
    const int rA   = t >> 4;           // row 0..15 ; rB = rA + 16
    const long long baseSD = (long long)b * SD;

    // ---- contiguous vec4 loads: thread owns rows rA and rA+16, 4 cols each ----
    const float4* m4r = (const float4*)(mem_r + baseSD);
    const float4* m4i = (const float4*)(mem_i + baseSD);
    const float4 mrA = m4r[t];
    const float4 mrB = m4r[t + 256];
    const float4 miA = m4i[t];
    const float4 miB = m4i[t + 256];

    // ---- stage gw into SMEM (coalesced; needed for broadcast in logits) ----
    if (t < 64) {
        gwr[t] = gw_r[(long long)b * D_ + t];
    } else if (t < 128) {
        gwi[t - 64] = gw_i[(long long)b * D_ + (t - 64)];
    }
    __syncthreads();

    // per-thread gw slices (registers, reused 3x)
    const float4 gwr4 = ((const float4*)gwr)[sub];
    const float4 gwi4 = ((const float4*)gwi)[sub];

    // ---- sim for rows rA, rA+16 : partial dot + 16-lane butterfly ----
    {
        float accA = dot4(mrA, gwr4) + dot4(miA, gwi4);
        float accB = dot4(mrB, gwr4) + dot4(miB, gwi4);
        #pragma unroll
        for (int o = 8; o; o >>= 1) {
            accA += __shfl_xor_sync(0xffffffffu, accA, o);
            accB += __shfl_xor_sync(0xffffffffu, accB, o);
        }
        if (sub == 0) {
            sim[rA]      = accA;
            sim[rA + 16] = accB;
        }
    }

    // ---- logits partials: warp w owns j in [16w, 16w+16), lane l owns s=l ----
    {
        const int j0 = warp * 16;
        float lacc = 0.0f;
        #pragma unroll
        for (int i = 0; i < 16; i++) {
            const int j = j0 + i;
            const float f = (j < 64) ? gwr[j] : gwi[j - 64];   // broadcast LDS
            lacc = fmaf(f, Wa[j * S_ + lane], lacc);           // coalesced LDG
        }
        wlog[warp][lane] = lacc;
    }
    __syncthreads();

    if (warp == 0) {
        // ---- attention softmax over S=32 ----
        const float v = sim[lane];
        float m = v;
        #pragma unroll
        for (int o = 16; o; o >>= 1) m = fmaxf(m, __shfl_xor_sync(0xffffffffu, m, o));
        const float e = __expf(v - m);
        float ssum = e;
        #pragma unroll
        for (int o = 16; o; o >>= 1) ssum += __shfl_xor_sync(0xffffffffu, ssum, o);
        attn[lane] = e / ssum;
    } else if (warp == 1) {
        // ---- write softmax + entropy + top-3 sparse ----
        float v = ba[lane];
        #pragma unroll
        for (int w = 0; w < 8; w++) v += wlog[w][lane];
        float m = v;
        #pragma unroll
        for (int o = 16; o; o >>= 1) m = fmaxf(m, __shfl_xor_sync(0xffffffffu, m, o));
        const float e = __expf(v - m);
        float ssum = e;
        #pragma unroll
        for (int o = 16; o; o >>= 1) ssum += __shfl_xor_sync(0xffffffffu, ssum, o);
        const float w_ = e / ssum;

        float ent = -w_ * __logf(w_ + 1e-10f);
        #pragma unroll
        for (int o = 16; o; o >>= 1) ent += __shfl_xor_sync(0xffffffffu, ent, o);
        if (lane == 0) atomicAdd(out + OFF_ENT, ent * (1.0f / (float)B_));

        float vv = w_;
        float sp = 0.0f;
        float sumTop = 0.0f;
        #pragma unroll
        for (int k = 0; k < KTOP; k++) {
            float mv = vv;
            int   mi = lane;
            #pragma unroll
            for (int o = 16; o; o >>= 1) {
                const float ov = __shfl_xor_sync(0xffffffffu, mv, o);
                const int   oi = __shfl_xor_sync(0xffffffffu, mi, o);
                if (ov > mv || (ov == mv && oi < mi)) { mv = ov; mi = oi; }
            }
            sumTop += mv;
            if (lane == mi) { sp = mv; vv = -INFINITY; }
        }
        sparse[lane] = sp / (sumTop + 1e-6f);
    } else if (warp == 2) {
        // ---- write gate ----
        float acc = 0.0f;
        #pragma unroll
        for (int i = 0; i < 4; i++) {
            const int j = lane + i * 32;
            const float f = (j < 64) ? gwr[j] : gwi[j - 64];
            acc = fmaf(f, Wg[j], acc);
        }
        #pragma unroll
        for (int o = 16; o; o >>= 1) acc += __shfl_xor_sync(0xffffffffu, acc, o);
        if (lane == 0) s_wg = 1.0f / (1.0f + __expf(-(acc + bg[0])));
    }
    __syncthreads();

    // ---- read-vector partials: combine both rows, fold lane halves ----
    {
        const float aA = attn[rA];
        const float aB = attn[rA + 16];
        float vr[4] = { aA*mrA.x + aB*mrB.x, aA*mrA.y + aB*mrB.y,
                        aA*mrA.z + aB*mrB.z, aA*mrA.w + aB*mrB.w };
        float vi[4] = { aA*miA.x + aB*miB.x, aA*miA.y + aB*miB.y,
                        aA*miA.z + aB*miB.z, aA*miA.w + aB*miB.w };
        #pragma unroll
        for (int i = 0; i < 4; i++) {
            vr[i] += __shfl_xor_sync(0xffffffffu, vr[i], 16);
            vi[i] += __shfl_xor_sync(0xffffffffu, vi[i], 16);
        }
        if (lane < 16) {
            ((float4*)&pr[warp][0])[lane]  = make_float4(vr[0], vr[1], vr[2], vr[3]);
            ((float4*)&pi_[warp][0])[lane] = make_float4(vi[0], vi[1], vi[2], vi[3]);
        }
    }

    // ---- memory update + LayerNorm (rows rA and rA+16; real and imag) ----
    {
        // gamma/beta straight from global: identical lines across all CTAs -> L1/L2 hits
        const float4 gr4 = ((const float4*)gamma_r)[sub];
        const float4 br4 = ((const float4*)beta_r)[sub];
        const float4 gi4 = ((const float4*)gamma_i)[sub];
        const float4 bi4 = ((const float4*)beta_i)[sub];
        const float sw   = s_wg;
        const float effA = sw * sparse[rA];
        const float effB = sw * sparse[rA + 16];
        const float omA  = 1.0f - effA;
        const float omB  = 1.0f - effB;

        float4* outR = (float4*)(out + OFF_NEXT_R + baseSD);
        float4* outI = (float4*)(out + OFF_NEXT_I + baseSD);

        #pragma unroll
        for (int part = 0; part < 4; part++) {
            // part 0: real rowA | 1: real rowB | 2: imag rowA | 3: imag rowB
            const float4 src = (part == 0) ? mrA : (part == 1) ? mrB
                             : (part == 2) ? miA : miB;
            const float4 g   = (part < 2) ? gwr4 : gwi4;
            const float  eff = (part & 1) ? effB : effA;
            const float  om  = (part & 1) ? omB  : omA;

            const float v0 = om * src.x + eff * g.x;
            const float v1 = om * src.y + eff * g.y;
            const float v2 = om * src.z + eff * g.z;
            const float v3 = om * src.w + eff * g.w;

            float sum = v0 + v1 + v2 + v3;
            float sq  = fmaf(v0, v0, fmaf(v1, v1, fmaf(v2, v2, v3 * v3)));
            #pragma unroll
            for (int o = 8; o; o >>= 1) {
                sum += __shfl_xor_sync(0xffffffffu, sum, o);
                sq  += __shfl_xor_sync(0xffffffffu, sq, o);
            }
            const float mean = sum * (1.0f / 64.0f);
            const float var  = sq * (1.0f / 64.0f) - mean * mean;
            const float rstd = rsqrtf(var + 1e-5f);

            const float4 gam = (part < 2) ? gr4 : gi4;
            const float4 bet = (part < 2) ? br4 : bi4;
            float4 o4;
            o4.x = fmaf((v0 - mean) * rstd, gam.x, bet.x);
            o4.y = fmaf((v1 - mean) * rstd, gam.y, bet.y);
            o4.z = fmaf((v2 - mean) * rstd, gam.z, bet.z);
            o4.w = fmaf((v3 - mean) * rstd, gam.w, bet.w);

            float4* dst = (part < 2) ? outR : outI;
            dst[(part & 1) ? (t + 256) : t] = o4;
        }
    }

    // ---- final read-vector reduction ----
    __syncthreads();
    if (t < 128) {
        const int d = t & 63;
        const float* src = (t < 64) ? &pr[0][0] : &pi_[0][0];
        float s = 0.0f;
        #pragma unroll
        for (int w = 0; w < 8; w++) s += src[w * D_ + d];
        const long long off = ((t < 64) ? OFF_READ_R : OFF_READ_I) + (long long)b * D_ + d;
        out[off] = s;
    }
}

extern "C" void kernel_launch(void* const* d_in, const int* in_sizes, int n_in,
                              void* d_out, int out_size)
{
    const float* gw_r    = (const float*)d_in[0];
    const float* gw_i    = (const float*)d_in[1];
    const float* mem_r   = (const float*)d_in[2];
    const float* mem_i   = (const float*)d_in[3];
    const float* Wg      = (const float*)d_in[4];
    const float* bg      = (const float*)d_in[5];
    const float* Wa      = (const float*)d_in[6];
    const float* ba      = (const float*)d_in[7];
    const float* gamma_r = (const float*)d_in[8];
    const float* beta_r  = (const float*)d_in[9];
    const float* gamma_i = (const float*)d_in[10];
    const float* beta_i  = (const float*)d_in[11];
    float* out = (float*)d_out;

    am_init_kernel<<<1, 1>>>(out);
    am_fused_kernel<<<B_, 256>>>(gw_r, gw_i, mem_r, mem_i, Wg, bg, Wa, ba,
                                 gamma_r, beta_r, gamma_i, beta_i, out);
}

// round 9
// speedup vs baseline: 1.3512x; 1.1177x over previous
#include <cuda_runtime.h>
#include <math.h>

#define B_ 16384
#define S_ 32
#define D_ 64
#define KTOP 3

constexpr int SD = S_ * D_;
constexpr long long OFF_READ_R = 0;
constexpr long long OFF_READ_I = (long long)B_ * D_;
constexpr long long OFF_NEXT_R = 2LL * B_ * D_;
constexpr long long OFF_NEXT_I = OFF_NEXT_R + (long long)B_ * SD;
constexpr long long OFF_ENT    = OFF_NEXT_I + (long long)B_ * SD;

__global__ void am_init_kernel(float* __restrict__ out) {
    out[OFF_ENT] = 0.0f;
}

__device__ __forceinline__ float dot4(float4 a, float4 b) {
    float s = a.x * b.x;
    s = fmaf(a.y, b.y, s);
    s = fmaf(a.z, b.z, s);
    s = fmaf(a.w, b.w, s);
    return s;
}

#define FULLM 0xffffffffu

__global__ __launch_bounds__(256, 5) void am_fused_kernel(
    const float* __restrict__ gw_r,  const float* __restrict__ gw_i,
    const float* __restrict__ mem_r, const float* __restrict__ mem_i,
    const float* __restrict__ Wg,    const float* __restrict__ bg,
    const float* __restrict__ Wa,    const float* __restrict__ ba,
    const float* __restrict__ gamma_r, const float* __restrict__ beta_r,
    const float* __restrict__ gamma_i, const float* __restrict__ beta_i,
    float* __restrict__ out)
{
    __shared__ __align__(16) float gwr[D_];
    __shared__ __align__(16) float gwi[D_];
    __shared__ float sim[S_], attn[S_], sparse[S_];
    __shared__ __align__(16) float wlog[8][S_];   // per-warp logit partials
    __shared__ __align__(16) float pr[8][D_];     // per-warp read_r partials
    __shared__ __align__(16) float pi_[8][D_];    // per-warp read_i partials
    __shared__ float s_wg;

    const int t    = threadIdx.x;
    const int b    = blockIdx.x;
    const int warp = t >> 5;
    const int lane = t & 31;
    const int sub  = t & 15;           // column group: cols 4*sub..4*sub+3
    const int rA   = t >> 4;           // row 0..15 ; rB = rA + 16
    const long long baseSD = (long long)b * SD;

    // ---- contiguous vec4 loads: thread owns rows rA and rA+16, 4 cols each ----
    const float4* m4r = (const float4*)(mem_r + baseSD);
    const float4* m4i = (const float4*)(mem_i + baseSD);
    const float4 mrA = m4r[t];
    const float4 mrB = m4r[t + 256];
    const float4 miA = m4i[t];
    const float4 miB = m4i[t + 256];

    // ---- stage gw into SMEM (coalesced; used for broadcasts) ----
    if (t < 64) {
        gwr[t] = gw_r[(long long)b * D_ + t];
    } else if (t < 128) {
        gwi[t - 64] = gw_i[(long long)b * D_ + (t - 64)];
    }
    __syncthreads();

    // per-thread gw slices (registers, reused 3x)
    const float4 gwr4 = ((const float4*)gwr)[sub];
    const float4 gwi4 = ((const float4*)gwi)[sub];

    // ---- sim for rows rA, rA+16 : reduce-scatter over 16 lanes (4 shfls) ----
    {
        const float accA = dot4(mrA, gwr4) + dot4(miA, gwi4);
        const float accB = dot4(mrB, gwr4) + dot4(miB, gwi4);
        const bool hi = (lane & 8);
        const float recv = __shfl_xor_sync(FULLM, hi ? accA : accB, 8);
        float acc = (hi ? accB : accA) + recv;
        acc += __shfl_xor_sync(FULLM, acc, 4);
        acc += __shfl_xor_sync(FULLM, acc, 2);
        acc += __shfl_xor_sync(FULLM, acc, 1);
        if (sub == 0) sim[rA]      = acc;   // low half holds rowA total
        if (sub == 8) sim[rA + 16] = acc;   // high half holds rowB total
    }

    // ---- logits partials: warp w owns j in [16w,16w+16) ----
    // lane = 8*g + k : g=row-within-quad (0..3), k=s-quad (0..7)
    // iteration i loads 4 Wa rows j = 16w + 4i + g as one float4 per lane.
    {
        const int g = lane >> 3;
        const int k = lane & 7;
        const float* flatsrc = (warp < 4) ? gwr : gwi;
        const int jb = (warp & 3) * 16;
        float4 lacc = make_float4(0.f, 0.f, 0.f, 0.f);
        #pragma unroll
        for (int i = 0; i < 4; i++) {
            const float f = flatsrc[jb + 4 * i + g];                 // LDS bcast x4
            const float4 wa = ((const float4*)Wa)[(warp * 16 + 4 * i + g) * 8 + k];
            lacc.x = fmaf(f, wa.x, lacc.x);
            lacc.y = fmaf(f, wa.y, lacc.y);
            lacc.z = fmaf(f, wa.z, lacc.z);
            lacc.w = fmaf(f, wa.w, lacc.w);
        }
        // reduce over the 4 g-groups (offsets 8, 16)
        lacc.x += __shfl_xor_sync(FULLM, lacc.x, 8);
        lacc.y += __shfl_xor_sync(FULLM, lacc.y, 8);
        lacc.z += __shfl_xor_sync(FULLM, lacc.z, 8);
        lacc.w += __shfl_xor_sync(FULLM, lacc.w, 8);
        lacc.x += __shfl_xor_sync(FULLM, lacc.x, 16);
        lacc.y += __shfl_xor_sync(FULLM, lacc.y, 16);
        lacc.z += __shfl_xor_sync(FULLM, lacc.z, 16);
        lacc.w += __shfl_xor_sync(FULLM, lacc.w, 16);
        if (lane < 8) ((float4*)&wlog[warp][0])[k] = lacc;
    }
    __syncthreads();

    if (warp == 0) {
        // ---- attention softmax over S=32 ----
        const float v = sim[lane];
        float m = v;
        #pragma unroll
        for (int o = 16; o; o >>= 1) m = fmaxf(m, __shfl_xor_sync(FULLM, m, o));
        const float e = __expf(v - m);
        float ssum = e;
        #pragma unroll
        for (int o = 16; o; o >>= 1) ssum += __shfl_xor_sync(FULLM, ssum, o);
        attn[lane] = e / ssum;
    } else if (warp == 1) {
        // ---- write softmax + entropy + top-3 sparse ----
        float v = ba[lane];
        #pragma unroll
        for (int w = 0; w < 8; w++) v += wlog[w][lane];
        float m = v;
        #pragma unroll
        for (int o = 16; o; o >>= 1) m = fmaxf(m, __shfl_xor_sync(FULLM, m, o));
        const float e = __expf(v - m);
        float ssum = e;
        #pragma unroll
        for (int o = 16; o; o >>= 1) ssum += __shfl_xor_sync(FULLM, ssum, o);
        const float w_ = e / ssum;

        float ent = -w_ * __logf(w_ + 1e-10f);
        #pragma unroll
        for (int o = 16; o; o >>= 1) ent += __shfl_xor_sync(FULLM, ent, o);
        if (lane == 0) atomicAdd(out + OFF_ENT, ent * (1.0f / (float)B_));

        float vv = w_;
        float sp = 0.0f;
        float sumTop = 0.0f;
        #pragma unroll
        for (int k = 0; k < KTOP; k++) {
            float mv = vv;
            int   mi = lane;
            #pragma unroll
            for (int o = 16; o; o >>= 1) {
                const float ov = __shfl_xor_sync(FULLM, mv, o);
                const int   oi = __shfl_xor_sync(FULLM, mi, o);
                if (ov > mv || (ov == mv && oi < mi)) { mv = ov; mi = oi; }
            }
            sumTop += mv;
            if (lane == mi) { sp = mv; vv = -INFINITY; }
        }
        sparse[lane] = sp / (sumTop + 1e-6f);
    } else if (warp == 2) {
        // ---- write gate ----
        float acc = 0.0f;
        #pragma unroll
        for (int i = 0; i < 4; i++) {
            const int j = lane + i * 32;
            const float f = (j < 64) ? gwr[j] : gwi[j - 64];
            acc = fmaf(f, Wg[j], acc);
        }
        #pragma unroll
        for (int o = 16; o; o >>= 1) acc += __shfl_xor_sync(FULLM, acc, o);
        if (lane == 0) s_wg = 1.0f / (1.0f + __expf(-(acc + bg[0])));
    }
    __syncthreads();

    // ---- read-vector partials: combine both rows, fold lane halves ----
    {
        const float aA = attn[rA];
        const float aB = attn[rA + 16];
        float vr[4] = { aA*mrA.x + aB*mrB.x, aA*mrA.y + aB*mrB.y,
                        aA*mrA.z + aB*mrB.z, aA*mrA.w + aB*mrB.w };
        float vi[4] = { aA*miA.x + aB*miB.x, aA*miA.y + aB*miB.y,
                        aA*miA.z + aB*miB.z, aA*miA.w + aB*miB.w };
        #pragma unroll
        for (int i = 0; i < 4; i++) {
            vr[i] += __shfl_xor_sync(FULLM, vr[i], 16);
            vi[i] += __shfl_xor_sync(FULLM, vi[i], 16);
        }
        if (lane < 16) {
            ((float4*)&pr[warp][0])[lane]  = make_float4(vr[0], vr[1], vr[2], vr[3]);
            ((float4*)&pi_[warp][0])[lane] = make_float4(vi[0], vi[1], vi[2], vi[3]);
        }
    }

    // ---- memory update + LayerNorm (parts: 0=realA, 1=realB, 2=imagA, 3=imagB) ----
    {
        const float sw   = s_wg;
        const float effA = sw * sparse[rA];
        const float effB = sw * sparse[rA + 16];
        const float omA  = 1.0f - effA;
        const float omB  = 1.0f - effB;

        // pass 1: per-part partial sum / sumsq over this thread's 4 elements
        float s_[4], q_[4];
        #pragma unroll
        for (int part = 0; part < 4; part++) {
            const float4 src = (part == 0) ? mrA : (part == 1) ? mrB
                             : (part == 2) ? miA : miB;
            const float4 g   = (part < 2) ? gwr4 : gwi4;
            const float  eff = (part & 1) ? effB : effA;
            const float  om  = (part & 1) ? omB  : omA;
            const float v0 = om * src.x + eff * g.x;
            const float v1 = om * src.y + eff * g.y;
            const float v2 = om * src.z + eff * g.z;
            const float v3 = om * src.w + eff * g.w;
            s_[part] = v0 + v1 + v2 + v3;
            q_[part] = fmaf(v0, v0, fmaf(v1, v1, fmaf(v2, v2, v3 * v3)));
        }

        // reduce-scatter over 16-lane group: o=8 splits real|imag, o=4 splits A|B
        const bool hi8 = (lane & 8);
        const float r0 = __shfl_xor_sync(FULLM, hi8 ? s_[0] : s_[2], 8);
        const float r1 = __shfl_xor_sync(FULLM, hi8 ? q_[0] : q_[2], 8);
        const float r2 = __shfl_xor_sync(FULLM, hi8 ? s_[1] : s_[3], 8);
        const float r3 = __shfl_xor_sync(FULLM, hi8 ? q_[1] : q_[3], 8);
        const float sa = (hi8 ? s_[2] : s_[0]) + r0;
        const float qa = (hi8 ? q_[2] : q_[0]) + r1;
        const float sb = (hi8 ? s_[3] : s_[1]) + r2;
        const float qb = (hi8 ? q_[3] : q_[1]) + r3;

        const bool hi4 = (lane & 4);
        const float rs = __shfl_xor_sync(FULLM, hi4 ? sa : sb, 4);
        const float rq = __shfl_xor_sync(FULLM, hi4 ? qa : qb, 4);
        float ss = (hi4 ? sb : sa) + rs;
        float qq = (hi4 ? qb : qa) + rq;

        ss += __shfl_xor_sync(FULLM, ss, 2);
        qq += __shfl_xor_sync(FULLM, qq, 2);
        ss += __shfl_xor_sync(FULLM, ss, 1);
        qq += __shfl_xor_sync(FULLM, qq, 1);

        // this lane now owns full stats for part p_own = (lane>>2)&3
        const float mean_m = ss * (1.0f / 64.0f);
        const float var_m  = qq * (1.0f / 64.0f) - mean_m * mean_m;
        const float rstd_m = rsqrtf(var_m + 1e-5f);

        // broadcast each part's (mean, rstd) from its owning quad
        float mean[4], rstd[4];
        #pragma unroll
        for (int p = 0; p < 4; p++) {
            const int src = (lane & 16) | (p << 2) | (lane & 3);
            mean[p] = __shfl_sync(FULLM, mean_m, src);
            rstd[p] = __shfl_sync(FULLM, rstd_m, src);
        }

        // gamma/beta straight from global: identical lines across CTAs -> cache hits
        const float4 gr4 = ((const float4*)gamma_r)[sub];
        const float4 br4 = ((const float4*)beta_r)[sub];
        const float4 gi4 = ((const float4*)gamma_i)[sub];
        const float4 bi4 = ((const float4*)beta_i)[sub];

        float4* outR = (float4*)(out + OFF_NEXT_R + baseSD);
        float4* outI = (float4*)(out + OFF_NEXT_I + baseSD);

        // pass 2: recompute v, normalize, store
        #pragma unroll
        for (int part = 0; part < 4; part++) {
            const float4 src = (part == 0) ? mrA : (part == 1) ? mrB
                             : (part == 2) ? miA : miB;
            const float4 g   = (part < 2) ? gwr4 : gwi4;
            const float  eff = (part & 1) ? effB : effA;
            const float  om  = (part & 1) ? omB  : omA;
            const float  mn  = mean[part];
            const float  rs2 = rstd[part];

            const float v0 = om * src.x + eff * g.x;
            const float v1 = om * src.y + eff * g.y;
            const float v2 = om * src.z + eff * g.z;
            const float v3 = om * src.w + eff * g.w;

            const float4 gam = (part < 2) ? gr4 : gi4;
            const float4 bet = (part < 2) ? br4 : bi4;
            float4 o4;
            o4.x = fmaf((v0 - mn) * rs2, gam.x, bet.x);
            o4.y = fmaf((v1 - mn) * rs2, gam.y, bet.y);
            o4.z = fmaf((v2 - mn) * rs2, gam.z, bet.z);
            o4.w = fmaf((v3 - mn) * rs2, gam.w, bet.w);

            float4* dst = (part < 2) ? outR : outI;
            dst[(part & 1) ? (t + 256) : t] = o4;
        }
    }

    // ---- final read-vector reduction ----
    __syncthreads();
    if (t < 128) {
        const int d = t & 63;
        const float* src = (t < 64) ? &pr[0][0] : &pi_[0][0];
        float s = 0.0f;
        #pragma unroll
        for (int w = 0; w < 8; w++) s += src[w * D_ + d];
        const long long off = ((t < 64) ? OFF_READ_R : OFF_READ_I) + (long long)b * D_ + d;
        out[off] = s;
    }
}

extern "C" void kernel_launch(void* const* d_in, const int* in_sizes, int n_in,
                              void* d_out, int out_size)
{
    const float* gw_r    = (const float*)d_in[0];
    const float* gw_i    = (const float*)d_in[1];
    const float* mem_r   = (const float*)d_in[2];
    const float* mem_i   = (const float*)d_in[3];
    const float* Wg      = (const float*)d_in[4];
    const float* bg      = (const float*)d_in[5];
    const float* Wa      = (const float*)d_in[6];
    const float* ba      = (const float*)d_in[7];
    const float* gamma_r = (const float*)d_in[8];
    const float* beta_r  = (const float*)d_in[9];
    const float* gamma_i = (const float*)d_in[10];
    const float* beta_i  = (const float*)d_in[11];
    float* out = (float*)d_out;

    am_init_kernel<<<1, 1>>>(out);
    am_fused_kernel<<<B_, 256>>>(gw_r, gw_i, mem_r, mem_i, Wg, bg, Wa, ba,
                                 gamma_r, beta_r, gamma_i, beta_i, out);
}

// round 10
// speedup vs baseline: 1.3667x; 1.0115x over previous
#include <cuda_runtime.h>
#include <math.h>

#define B_ 16384
#define S_ 32
#define D_ 64
#define KTOP 3

constexpr int SD = S_ * D_;
constexpr long long OFF_READ_R = 0;
constexpr long long OFF_READ_I = (long long)B_ * D_;
constexpr long long OFF_NEXT_R = 2LL * B_ * D_;
constexpr long long OFF_NEXT_I = OFF_NEXT_R + (long long)B_ * SD;
constexpr long long OFF_ENT    = OFF_NEXT_I + (long long)B_ * SD;

__global__ void am_init_kernel(float* __restrict__ out) {
    out[OFF_ENT] = 0.0f;
}

__device__ __forceinline__ float dot4(float4 a, float4 b) {
    float s = a.x * b.x;
    s = fmaf(a.y, b.y, s);
    s = fmaf(a.z, b.z, s);
    s = fmaf(a.w, b.w, s);
    return s;
}

#define FULLM 0xffffffffu

__global__ __launch_bounds__(256, 6) void am_fused_kernel(
    const float* __restrict__ gw_r,  const float* __restrict__ gw_i,
    const float* __restrict__ mem_r, const float* __restrict__ mem_i,
    const float* __restrict__ Wg,    const float* __restrict__ bg,
    const float* __restrict__ Wa,    const float* __restrict__ ba,
    const float* __restrict__ gamma_r, const float* __restrict__ beta_r,
    const float* __restrict__ gamma_i, const float* __restrict__ beta_i,
    float* __restrict__ out)
{
    __shared__ float sim[S_], attn[S_], sparse[S_];
    __shared__ __align__(16) float wlog[8][S_];   // per-warp logit partials
    __shared__ __align__(16) float pr[8][D_];     // per-warp read_r partials
    __shared__ __align__(16) float pi_[8][D_];    // per-warp read_i partials
    __shared__ float s_wg;

    const int t    = threadIdx.x;
    const int b    = blockIdx.x;
    const int warp = t >> 5;
    const int lane = t & 31;
    const int sub  = t & 15;           // column group: cols 4*sub..4*sub+3
    const int rA   = t >> 4;           // row 0..15 ; rB = rA + 16
    const long long baseSD = (long long)b * SD;
    const long long baseD  = (long long)b * D_;

    // ---- contiguous vec4 loads: thread owns rows rA and rA+16, 4 cols each ----
    const float4* m4r = (const float4*)(mem_r + baseSD);
    const float4* m4i = (const float4*)(mem_i + baseSD);
    const float4 mrA = m4r[t];
    const float4 mrB = m4r[t + 256];
    const float4 miA = m4i[t];
    const float4 miB = m4i[t + 256];

    // ---- gw slices: direct LDG (no SMEM staging, no barrier) ----
    const float4 gwr4 = ((const float4*)(gw_r + baseD))[sub];
    const float4 gwi4 = ((const float4*)(gw_i + baseD))[sub];

    // ---- sim for rows rA, rA+16 : reduce-scatter over 16 lanes (4 shfls) ----
    {
        const float accA = dot4(mrA, gwr4) + dot4(miA, gwi4);
        const float accB = dot4(mrB, gwr4) + dot4(miB, gwi4);
        const bool hi = (lane & 8);
        const float recv = __shfl_xor_sync(FULLM, hi ? accA : accB, 8);
        float acc = (hi ? accB : accA) + recv;
        acc += __shfl_xor_sync(FULLM, acc, 4);
        acc += __shfl_xor_sync(FULLM, acc, 2);
        acc += __shfl_xor_sync(FULLM, acc, 1);
        if (sub == 0) sim[rA]      = acc;   // low half holds rowA total
        if (sub == 8) sim[rA + 16] = acc;   // high half holds rowB total
    }

    // ---- logits partials: warp w owns j in [16w,16w+16) ----
    // lane = 8*g + k : g=row-within-quad (0..3), k=s-quad (0..7)
    {
        const int g = lane >> 3;
        const int k = lane & 7;
        const float* flatsrc = (warp < 4) ? (gw_r + baseD) : (gw_i + baseD);
        const int jb = (warp & 3) * 16;
        float4 lacc = make_float4(0.f, 0.f, 0.f, 0.f);
        #pragma unroll
        for (int i = 0; i < 4; i++) {
            const float f = flatsrc[jb + 4 * i + g];                 // LDG, L1 hit
            const float4 wa = ((const float4*)Wa)[(warp * 16 + 4 * i + g) * 8 + k];
            lacc.x = fmaf(f, wa.x, lacc.x);
            lacc.y = fmaf(f, wa.y, lacc.y);
            lacc.z = fmaf(f, wa.z, lacc.z);
            lacc.w = fmaf(f, wa.w, lacc.w);
        }
        lacc.x += __shfl_xor_sync(FULLM, lacc.x, 8);
        lacc.y += __shfl_xor_sync(FULLM, lacc.y, 8);
        lacc.z += __shfl_xor_sync(FULLM, lacc.z, 8);
        lacc.w += __shfl_xor_sync(FULLM, lacc.w, 8);
        lacc.x += __shfl_xor_sync(FULLM, lacc.x, 16);
        lacc.y += __shfl_xor_sync(FULLM, lacc.y, 16);
        lacc.z += __shfl_xor_sync(FULLM, lacc.z, 16);
        lacc.w += __shfl_xor_sync(FULLM, lacc.w, 16);
        if (lane < 8) ((float4*)&wlog[warp][0])[k] = lacc;
    }
    __syncthreads();

    if (warp == 0) {
        // ---- attention softmax over S=32 ----
        const float v = sim[lane];
        float m = v;
        #pragma unroll
        for (int o = 16; o; o >>= 1) m = fmaxf(m, __shfl_xor_sync(FULLM, m, o));
        const float e = __expf(v - m);
        float ssum = e;
        #pragma unroll
        for (int o = 16; o; o >>= 1) ssum += __shfl_xor_sync(FULLM, ssum, o);
        attn[lane] = e / ssum;
    } else if (warp == 1) {
        // ---- write softmax + entropy + top-3 sparse ----
        float v = ba[lane];
        #pragma unroll
        for (int w = 0; w < 8; w++) v += wlog[w][lane];
        float m = v;
        #pragma unroll
        for (int o = 16; o; o >>= 1) m = fmaxf(m, __shfl_xor_sync(FULLM, m, o));
        const float e = __expf(v - m);
        float ssum = e;
        #pragma unroll
        for (int o = 16; o; o >>= 1) ssum += __shfl_xor_sync(FULLM, ssum, o);
        const float w_ = e / ssum;

        float ent = -w_ * __logf(w_ + 1e-10f);
        #pragma unroll
        for (int o = 16; o; o >>= 1) ent += __shfl_xor_sync(FULLM, ent, o);
        if (lane == 0) atomicAdd(out + OFF_ENT, ent * (1.0f / (float)B_));

        float vv = w_;
        float sp = 0.0f;
        float sumTop = 0.0f;
        #pragma unroll
        for (int k = 0; k < KTOP; k++) {
            float mv = vv;
            int   mi = lane;
            #pragma unroll
            for (int o = 16; o; o >>= 1) {
                const float ov = __shfl_xor_sync(FULLM, mv, o);
                const int   oi = __shfl_xor_sync(FULLM, mi, o);
                if (ov > mv || (ov == mv && oi < mi)) { mv = ov; mi = oi; }
            }
            sumTop += mv;
            if (lane == mi) { sp = mv; vv = -INFINITY; }
        }
        sparse[lane] = sp / (sumTop + 1e-6f);
    } else if (warp == 2) {
        // ---- write gate ----
        float acc = 0.0f;
        #pragma unroll
        for (int i = 0; i < 4; i++) {
            const int j = lane + i * 32;
            const float f = (j < 64) ? gw_r[baseD + j] : gw_i[baseD + j - 64];
            acc = fmaf(f, Wg[j], acc);
        }
        #pragma unroll
        for (int o = 16; o; o >>= 1) acc += __shfl_xor_sync(FULLM, acc, o);
        if (lane == 0) s_wg = 1.0f / (1.0f + __expf(-(acc + bg[0])));
    }
    __syncthreads();

    // ---- read-vector partials: combine both rows, fold lane halves ----
    {
        const float aA = attn[rA];
        const float aB = attn[rA + 16];
        float vr[4] = { aA*mrA.x + aB*mrB.x, aA*mrA.y + aB*mrB.y,
                        aA*mrA.z + aB*mrB.z, aA*mrA.w + aB*mrB.w };
        float vi[4] = { aA*miA.x + aB*miB.x, aA*miA.y + aB*miB.y,
                        aA*miA.z + aB*miB.z, aA*miA.w + aB*miB.w };
        #pragma unroll
        for (int i = 0; i < 4; i++) {
            vr[i] += __shfl_xor_sync(FULLM, vr[i], 16);
            vi[i] += __shfl_xor_sync(FULLM, vi[i], 16);
        }
        if (lane < 16) {
            ((float4*)&pr[warp][0])[lane]  = make_float4(vr[0], vr[1], vr[2], vr[3]);
            ((float4*)&pi_[warp][0])[lane] = make_float4(vi[0], vi[1], vi[2], vi[3]);
        }
    }

    // ---- memory update + LayerNorm (parts: 0=realA, 1=realB, 2=imagA, 3=imagB) ----
    {
        const float sw   = s_wg;
        const float effA = sw * sparse[rA];
        const float effB = sw * sparse[rA + 16];
        const float omA  = 1.0f - effA;
        const float omB  = 1.0f - effB;

        // pass 1: per-part partial sum / sumsq over this thread's 4 elements
        float s_[4], q_[4];
        #pragma unroll
        for (int part = 0; part < 4; part++) {
            const float4 src = (part == 0) ? mrA : (part == 1) ? mrB
                             : (part == 2) ? miA : miB;
            const float4 g   = (part < 2) ? gwr4 : gwi4;
            const float  eff = (part & 1) ? effB : effA;
            const float  om  = (part & 1) ? omB  : omA;
            const float v0 = om * src.x + eff * g.x;
            const float v1 = om * src.y + eff * g.y;
            const float v2 = om * src.z + eff * g.z;
            const float v3 = om * src.w + eff * g.w;
            s_[part] = v0 + v1 + v2 + v3;
            q_[part] = fmaf(v0, v0, fmaf(v1, v1, fmaf(v2, v2, v3 * v3)));
        }

        // reduce-scatter over 16-lane group: o=8 splits real|imag, o=4 splits A|B
        const bool hi8 = (lane & 8);
        const float r0 = __shfl_xor_sync(FULLM, hi8 ? s_[0] : s_[2], 8);
        const float r1 = __shfl_xor_sync(FULLM, hi8 ? q_[0] : q_[2], 8);
        const float r2 = __shfl_xor_sync(FULLM, hi8 ? s_[1] : s_[3], 8);
        const float r3 = __shfl_xor_sync(FULLM, hi8 ? q_[1] : q_[3], 8);
        const float sa = (hi8 ? s_[2] : s_[0]) + r0;
        const float qa = (hi8 ? q_[2] : q_[0]) + r1;
        const float sb = (hi8 ? s_[3] : s_[1]) + r2;
        const float qb = (hi8 ? q_[3] : q_[1]) + r3;

        const bool hi4 = (lane & 4);
        const float rs = __shfl_xor_sync(FULLM, hi4 ? sa : sb, 4);
        const float rq = __shfl_xor_sync(FULLM, hi4 ? qa : qb, 4);
        float ss = (hi4 ? sb : sa) + rs;
        float qq = (hi4 ? qb : qa) + rq;

        ss += __shfl_xor_sync(FULLM, ss, 2);
        qq += __shfl_xor_sync(FULLM, qq, 2);
        ss += __shfl_xor_sync(FULLM, ss, 1);
        qq += __shfl_xor_sync(FULLM, qq, 1);

        // this lane now owns full stats for part p_own = (lane>>2)&3
        const float mean_m = ss * (1.0f / 64.0f);
        const float var_m  = qq * (1.0f / 64.0f) - mean_m * mean_m;
        const float rstd_m = rsqrtf(var_m + 1e-5f);

        // broadcast each part's (mean, rstd) from its owning quad
        float mean[4], rstd[4];
        #pragma unroll
        for (int p = 0; p < 4; p++) {
            const int src = (lane & 16) | (p << 2) | (lane & 3);
            mean[p] = __shfl_sync(FULLM, mean_m, src);
            rstd[p] = __shfl_sync(FULLM, rstd_m, src);
        }

        // gamma/beta straight from global: identical lines across CTAs -> cache hits
        const float4 gr4 = ((const float4*)gamma_r)[sub];
        const float4 br4 = ((const float4*)beta_r)[sub];
        const float4 gi4 = ((const float4*)gamma_i)[sub];
        const float4 bi4 = ((const float4*)beta_i)[sub];

        float4* outR = (float4*)(out + OFF_NEXT_R + baseSD);
        float4* outI = (float4*)(out + OFF_NEXT_I + baseSD);

        // pass 2: recompute v, normalize, store
        #pragma unroll
        for (int part = 0; part < 4; part++) {
            const float4 src = (part == 0) ? mrA : (part == 1) ? mrB
                             : (part == 2) ? miA : miB;
            const float4 g   = (part < 2) ? gwr4 : gwi4;
            const float  eff = (part & 1) ? effB : effA;
            const float  om  = (part & 1) ? omB  : omA;
            const float  mn  = mean[part];
            const float  rs2 = rstd[part];

            const float v0 = om * src.x + eff * g.x;
            const float v1 = om * src.y + eff * g.y;
            const float v2 = om * src.z + eff * g.z;
            const float v3 = om * src.w + eff * g.w;

            const float4 gam = (part < 2) ? gr4 : gi4;
            const float4 bet = (part < 2) ? br4 : bi4;
            float4 o4;
            o4.x = fmaf((v0 - mn) * rs2, gam.x, bet.x);
            o4.y = fmaf((v1 - mn) * rs2, gam.y, bet.y);
            o4.z = fmaf((v2 - mn) * rs2, gam.z, bet.z);
            o4.w = fmaf((v3 - mn) * rs2, gam.w, bet.w);

            float4* dst = (part < 2) ? outR : outI;
            dst[(part & 1) ? (t + 256) : t] = o4;
        }
    }

    // ---- final read-vector reduction ----
    __syncthreads();
    if (t < 128) {
        const int d = t & 63;
        const float* src = (t < 64) ? &pr[0][0] : &pi_[0][0];
        float s = 0.0f;
        #pragma unroll
        for (int w = 0; w < 8; w++) s += src[w * D_ + d];
        const long long off = ((t < 64) ? OFF_READ_R : OFF_READ_I) + (long long)b * D_ + d;
        out[off] = s;
    }
}

extern "C" void kernel_launch(void* const* d_in, const int* in_sizes, int n_in,
                              void* d_out, int out_size)
{
    const float* gw_r    = (const float*)d_in[0];
    const float* gw_i    = (const float*)d_in[1];
    const float* mem_r   = (const float*)d_in[2];
    const float* mem_i   = (const float*)d_in[3];
    const float* Wg      = (const float*)d_in[4];
    const float* bg      = (const float*)d_in[5];
    const float* Wa      = (const float*)d_in[6];
    const float* ba      = (const float*)d_in[7];
    const float* gamma_r = (const float*)d_in[8];
    const float* beta_r  = (const float*)d_in[9];
    const float* gamma_i = (const float*)d_in[10];
    const float* beta_i  = (const float*)d_in[11];
    float* out = (float*)d_out;

    am_init_kernel<<<1, 1>>>(out);
    am_fused_kernel<<<B_, 256>>>(gw_r, gw_i, mem_r, mem_i, Wg, bg, Wa, ba,
                                 gamma_r, beta_r, gamma_i, beta_i, out);
}

// round 11
// speedup vs baseline: 1.4643x; 1.0714x over previous
#include <cuda_runtime.h>
#include <math.h>

#define B_ 16384
#define S_ 32
#define D_ 64
#define KTOP 3

constexpr int SD = S_ * D_;
constexpr long long OFF_READ_R = 0;
constexpr long long OFF_READ_I = (long long)B_ * D_;
constexpr long long OFF_NEXT_R = 2LL * B_ * D_;
constexpr long long OFF_NEXT_I = OFF_NEXT_R + (long long)B_ * SD;
constexpr long long OFF_ENT    = OFF_NEXT_I + (long long)B_ * SD;

__global__ void am_init_kernel(float* __restrict__ out) {
    out[OFF_ENT] = 0.0f;
}

__device__ __forceinline__ float dot4(float4 a, float4 b) {
    float s = a.x * b.x;
    s = fmaf(a.y, b.y, s);
    s = fmaf(a.z, b.z, s);
    s = fmaf(a.w, b.w, s);
    return s;
}

#define FULLM 0xffffffffu

// order-preserving float -> int key (involution); works for any finite/inf floats
__device__ __forceinline__ int f2key(float f) {
    int i = __float_as_int(f);
    return i ^ ((i >> 31) & 0x7fffffff);
}
__device__ __forceinline__ float key2f(int k) {
    return __int_as_float(k ^ ((k >> 31) & 0x7fffffff));
}
// single-instruction warp max of a float (any sign)
__device__ __forceinline__ float warp_fmax(float v) {
    return key2f(__reduce_max_sync(FULLM, f2key(v)));
}

__global__ __launch_bounds__(256, 6) void am_fused_kernel(
    const float* __restrict__ gw_r,  const float* __restrict__ gw_i,
    const float* __restrict__ mem_r, const float* __restrict__ mem_i,
    const float* __restrict__ Wg,    const float* __restrict__ bg,
    const float* __restrict__ Wa,    const float* __restrict__ ba,
    const float* __restrict__ gamma_r, const float* __restrict__ beta_r,
    const float* __restrict__ gamma_i, const float* __restrict__ beta_i,
    float* __restrict__ out)
{
    __shared__ float sim[S_], attn[S_], sparse[S_];
    __shared__ __align__(16) float wlog[8][S_];   // per-warp logit partials
    __shared__ __align__(16) float pr[8][D_];     // per-warp read_r partials
    __shared__ __align__(16) float pi_[8][D_];    // per-warp read_i partials
    __shared__ float s_wg;

    const int t    = threadIdx.x;
    const int b    = blockIdx.x;
    const int warp = t >> 5;
    const int lane = t & 31;
    const int sub  = t & 15;           // column group: cols 4*sub..4*sub+3
    const int rA   = t >> 4;           // row 0..15 ; rB = rA + 16
    const long long baseSD = (long long)b * SD;
    const long long baseD  = (long long)b * D_;

    // ---- contiguous vec4 loads: thread owns rows rA and rA+16, 4 cols each ----
    const float4* m4r = (const float4*)(mem_r + baseSD);
    const float4* m4i = (const float4*)(mem_i + baseSD);
    const float4 mrA = m4r[t];
    const float4 mrB = m4r[t + 256];
    const float4 miA = m4i[t];
    const float4 miB = m4i[t + 256];

    // ---- gw slices: direct LDG (no SMEM staging, no barrier) ----
    const float4 gwr4 = ((const float4*)(gw_r + baseD))[sub];
    const float4 gwi4 = ((const float4*)(gw_i + baseD))[sub];

    // ---- sim for rows rA, rA+16 : reduce-scatter over 16 lanes (4 shfls) ----
    {
        const float accA = dot4(mrA, gwr4) + dot4(miA, gwi4);
        const float accB = dot4(mrB, gwr4) + dot4(miB, gwi4);
        const bool hi = (lane & 8);
        const float recv = __shfl_xor_sync(FULLM, hi ? accA : accB, 8);
        float acc = (hi ? accB : accA) + recv;
        acc += __shfl_xor_sync(FULLM, acc, 4);
        acc += __shfl_xor_sync(FULLM, acc, 2);
        acc += __shfl_xor_sync(FULLM, acc, 1);
        if (sub == 0) sim[rA]      = acc;   // low half holds rowA total
        if (sub == 8) sim[rA + 16] = acc;   // high half holds rowB total
    }

    // ---- logits partials: warp w owns j in [16w,16w+16) ----
    // lane = 8*g + k : g=row-within-quad (0..3), k=s-quad (0..7)
    {
        const int g = lane >> 3;
        const int k = lane & 7;
        const float* flatsrc = (warp < 4) ? (gw_r + baseD) : (gw_i + baseD);
        const int jb = (warp & 3) * 16;
        float4 lacc = make_float4(0.f, 0.f, 0.f, 0.f);
        #pragma unroll
        for (int i = 0; i < 4; i++) {
            const float f = flatsrc[jb + 4 * i + g];                 // LDG, L1 hit
            const float4 wa = ((const float4*)Wa)[(warp * 16 + 4 * i + g) * 8 + k];
            lacc.x = fmaf(f, wa.x, lacc.x);
            lacc.y = fmaf(f, wa.y, lacc.y);
            lacc.z = fmaf(f, wa.z, lacc.z);
            lacc.w = fmaf(f, wa.w, lacc.w);
        }
        lacc.x += __shfl_xor_sync(FULLM, lacc.x, 8);
        lacc.y += __shfl_xor_sync(FULLM, lacc.y, 8);
        lacc.z += __shfl_xor_sync(FULLM, lacc.z, 8);
        lacc.w += __shfl_xor_sync(FULLM, lacc.w, 8);
        lacc.x += __shfl_xor_sync(FULLM, lacc.x, 16);
        lacc.y += __shfl_xor_sync(FULLM, lacc.y, 16);
        lacc.z += __shfl_xor_sync(FULLM, lacc.z, 16);
        lacc.w += __shfl_xor_sync(FULLM, lacc.w, 16);
        if (lane < 8) ((float4*)&wlog[warp][0])[k] = lacc;
    }
    __syncthreads();

    if (warp == 0) {
        // ---- attention softmax over S=32 (redux max, shfl sum) ----
        const float v = sim[lane];
        const float m = warp_fmax(v);
        const float e = __expf(v - m);
        float ssum = e;
        #pragma unroll
        for (int o = 16; o; o >>= 1) ssum += __shfl_xor_sync(FULLM, ssum, o);
        attn[lane] = e / ssum;
    } else if (warp == 1) {
        // ---- write softmax + entropy + top-3 sparse ----
        float v = ba[lane];
        #pragma unroll
        for (int w = 0; w < 8; w++) v += wlog[w][lane];
        const float m = warp_fmax(v);
        const float e = __expf(v - m);
        float ssum = e;
        #pragma unroll
        for (int o = 16; o; o >>= 1) ssum += __shfl_xor_sync(FULLM, ssum, o);
        const float w_ = e / ssum;

        float ent = -w_ * __logf(w_ + 1e-10f);
        #pragma unroll
        for (int o = 16; o; o >>= 1) ent += __shfl_xor_sync(FULLM, ent, o);
        if (lane == 0) atomicAdd(out + OFF_ENT, ent * (1.0f / (float)B_));

        // top-3 via redux-max + ballot (probs > 0, so int-bit order == float order;
        // knocked-out lanes hold -INF whose key is very negative)
        float vv = w_;
        float sp = 0.0f;
        float sumTop = 0.0f;
        #pragma unroll
        for (int k = 0; k < KTOP; k++) {
            const int mkey = __reduce_max_sync(FULLM, __float_as_int(vv));
            const float mv = __int_as_float(mkey);
            const unsigned msk = __ballot_sync(FULLM, vv == mv);
            const int mi = __ffs(msk) - 1;      // tie -> lowest index
            sumTop += mv;
            if (lane == mi) { sp = mv; vv = -INFINITY; }
        }
        sparse[lane] = sp / (sumTop + 1e-6f);
    } else if (warp == 2) {
        // ---- write gate ----
        float acc = 0.0f;
        #pragma unroll
        for (int i = 0; i < 4; i++) {
            const int j = lane + i * 32;
            const float f = (j < 64) ? gw_r[baseD + j] : gw_i[baseD + j - 64];
            acc = fmaf(f, Wg[j], acc);
        }
        #pragma unroll
        for (int o = 16; o; o >>= 1) acc += __shfl_xor_sync(FULLM, acc, o);
        if (lane == 0) s_wg = 1.0f / (1.0f + __expf(-(acc + bg[0])));
    }
    __syncthreads();

    // ---- read-vector partials: combine both rows, fold lane halves ----
    {
        const float aA = attn[rA];
        const float aB = attn[rA + 16];
        float vr[4] = { aA*mrA.x + aB*mrB.x, aA*mrA.y + aB*mrB.y,
                        aA*mrA.z + aB*mrB.z, aA*mrA.w + aB*mrB.w };
        float vi[4] = { aA*miA.x + aB*miB.x, aA*miA.y + aB*miB.y,
                        aA*miA.z + aB*miB.z, aA*miA.w + aB*miB.w };
        #pragma unroll
        for (int i = 0; i < 4; i++) {
            vr[i] += __shfl_xor_sync(FULLM, vr[i], 16);
            vi[i] += __shfl_xor_sync(FULLM, vi[i], 16);
        }
        if (lane < 16) {
            ((float4*)&pr[warp][0])[lane]  = make_float4(vr[0], vr[1], vr[2], vr[3]);
            ((float4*)&pi_[warp][0])[lane] = make_float4(vi[0], vi[1], vi[2], vi[3]);
        }
    }

    // ---- memory update + LayerNorm (parts: 0=realA, 1=realB, 2=imagA, 3=imagB) ----
    {
        const float sw   = s_wg;
        const float effA = sw * sparse[rA];
        const float effB = sw * sparse[rA + 16];
        const float omA  = 1.0f - effA;
        const float omB  = 1.0f - effB;

        // pass 1: per-part partial sum / sumsq over this thread's 4 elements
        float s_[4], q_[4];
        #pragma unroll
        for (int part = 0; part < 4; part++) {
            const float4 src = (part == 0) ? mrA : (part == 1) ? mrB
                             : (part == 2) ? miA : miB;
            const float4 g   = (part < 2) ? gwr4 : gwi4;
            const float  eff = (part & 1) ? effB : effA;
            const float  om  = (part & 1) ? omB  : omA;
            const float v0 = om * src.x + eff * g.x;
            const float v1 = om * src.y + eff * g.y;
            const float v2 = om * src.z + eff * g.z;
            const float v3 = om * src.w + eff * g.w;
            s_[part] = v0 + v1 + v2 + v3;
            q_[part] = fmaf(v0, v0, fmaf(v1, v1, fmaf(v2, v2, v3 * v3)));
        }

        // reduce-scatter over 16-lane group: o=8 splits real|imag, o=4 splits A|B
        const bool hi8 = (lane & 8);
        const float r0 = __shfl_xor_sync(FULLM, hi8 ? s_[0] : s_[2], 8);
        const float r1 = __shfl_xor_sync(FULLM, hi8 ? q_[0] : q_[2], 8);
        const float r2 = __shfl_xor_sync(FULLM, hi8 ? s_[1] : s_[3], 8);
        const float r3 = __shfl_xor_sync(FULLM, hi8 ? q_[1] : q_[3], 8);
        const float sa = (hi8 ? s_[2] : s_[0]) + r0;
        const float qa = (hi8 ? q_[2] : q_[0]) + r1;
        const float sb = (hi8 ? s_[3] : s_[1]) + r2;
        const float qb = (hi8 ? q_[3] : q_[1]) + r3;

        const bool hi4 = (lane & 4);
        const float rs = __shfl_xor_sync(FULLM, hi4 ? sa : sb, 4);
        const float rq = __shfl_xor_sync(FULLM, hi4 ? qa : qb, 4);
        float ss = (hi4 ? sb : sa) + rs;
        float qq = (hi4 ? qb : qa) + rq;

        ss += __shfl_xor_sync(FULLM, ss, 2);
        qq += __shfl_xor_sync(FULLM, qq, 2);
        ss += __shfl_xor_sync(FULLM, ss, 1);
        qq += __shfl_xor_sync(FULLM, qq, 1);

        // this lane now owns full stats for part p_own = (lane>>2)&3
        const float mean_m = ss * (1.0f / 64.0f);
        const float var_m  = qq * (1.0f / 64.0f) - mean_m * mean_m;
        const float rstd_m = rsqrtf(var_m + 1e-5f);

        // broadcast each part's (mean, rstd) from its owning quad
        float mean[4], rstd[4];
        #pragma unroll
        for (int p = 0; p < 4; p++) {
            const int src = (lane & 16) | (p << 2) | (lane & 3);
            mean[p] = __shfl_sync(FULLM, mean_m, src);
            rstd[p] = __shfl_sync(FULLM, rstd_m, src);
        }

        // gamma/beta straight from global: identical lines across CTAs -> cache hits
        const float4 gr4 = ((const float4*)gamma_r)[sub];
        const float4 br4 = ((const float4*)beta_r)[sub];
        const float4 gi4 = ((const float4*)gamma_i)[sub];
        const float4 bi4 = ((const float4*)beta_i)[sub];

        float4* outR = (float4*)(out + OFF_NEXT_R + baseSD);
        float4* outI = (float4*)(out + OFF_NEXT_I + baseSD);

        // pass 2: recompute v, normalize, store
        #pragma unroll
        for (int part = 0; part < 4; part++) {
            const float4 src = (part == 0) ? mrA : (part == 1) ? mrB
                             : (part == 2) ? miA : miB;
            const float4 g   = (part < 2) ? gwr4 : gwi4;
            const float  eff = (part & 1) ? effB : effA;
            const float  om  = (part & 1) ? omB  : omA;
            const float  mn  = mean[part];
            const float  rs2 = rstd[part];

            const float v0 = om * src.x + eff * g.x;
            const float v1 = om * src.y + eff * g.y;
            const float v2 = om * src.z + eff * g.z;
            const float v3 = om * src.w + eff * g.w;

            const float4 gam = (part < 2) ? gr4 : gi4;
            const float4 bet = (part < 2) ? br4 : bi4;
            float4 o4;
            o4.x = fmaf((v0 - mn) * rs2, gam.x, bet.x);
            o4.y = fmaf((v1 - mn) * rs2, gam.y, bet.y);
            o4.z = fmaf((v2 - mn) * rs2, gam.z, bet.z);
            o4.w = fmaf((v3 - mn) * rs2, gam.w, bet.w);

            float4* dst = (part < 2) ? outR : outI;
            dst[(part & 1) ? (t + 256) : t] = o4;
        }
    }

    // ---- final read-vector reduction ----
    __syncthreads();
    if (t < 128) {
        const int d = t & 63;
        const float* src = (t < 64) ? &pr[0][0] : &pi_[0][0];
        float s = 0.0f;
        #pragma unroll
        for (int w = 0; w < 8; w++) s += src[w * D_ + d];
        const long long off = ((t < 64) ? OFF_READ_R : OFF_READ_I) + (long long)b * D_ + d;
        out[off] = s;
    }
}

extern "C" void kernel_launch(void* const* d_in, const int* in_sizes, int n_in,
                              void* d_out, int out_size)
{
    const float* gw_r    = (const float*)d_in[0];
    const float* gw_i    = (const float*)d_in[1];
    const float* mem_r   = (const float*)d_in[2];
    const float* mem_i   = (const float*)d_in[3];
    const float* Wg      = (const float*)d_in[4];
    const float* bg      = (const float*)d_in[5];
    const float* Wa      = (const float*)d_in[6];
    const float* ba      = (const float*)d_in[7];
    const float* gamma_r = (const float*)d_in[8];
    const float* beta_r  = (const float*)d_in[9];
    const float* gamma_i = (const float*)d_in[10];
    const float* beta_i  = (const float*)d_in[11];
    float* out = (float*)d_out;

    am_init_kernel<<<1, 1>>>(out);
    am_fused_kernel<<<B_, 256>>>(gw_r, gw_i, mem_r, mem_i, Wg, bg, Wa, ba,
                                 gamma_r, beta_r, gamma_i, beta_i, out);
}